// round 1
// baseline (speedup 1.0000x reference)
#include <cuda_runtime.h>
#include <stdint.h>

#define NLV 16
#define LOG2T 19
#define TSIZE (1u << LOG2T)
#define TMASK (TSIZE - 1u)
#define BASE_RES 16
#define BLK 256
#define PAD 36  // floats per point-row in smem staging (33 rounded to mult of 4, +bank skew)

__global__ __launch_bounds__(BLK) void hash_enc_kernel(
    const float* __restrict__ x,
    const float* __restrict__ bb,
    const float* __restrict__ table,
    float* __restrict__ out,
    float* __restrict__ mask_out,
    int n, int write_mask)
{
    __shared__ __align__(16) float s[BLK * PAD];

    const int tid = threadIdx.x;
    const long pt = (long)blockIdx.x * BLK + tid;
    const bool active = pt < n;

    float xnx = 0.f, xny = 0.f, xnz = 0.f;
    if (active) {
        const float bx0 = bb[0], by0 = bb[1], bz0 = bb[2];
        const float bx1 = bb[3], by1 = bb[4], bz1 = bb[5];
        const float px = x[pt * 3 + 0];
        const float py = x[pt * 3 + 1];
        const float pz = x[pt * 3 + 2];
        xnx = (px - bx0) / (bx1 - bx0);
        xny = (py - by0) / (by1 - by0);
        xnz = (pz - bz0) / (bz1 - bz0);
        if (write_mask) {
            const bool m = (xnx > 0.f) & (xnx < 1.f) &
                           (xny > 0.f) & (xny < 1.f) &
                           (xnz > 0.f) & (xnz < 1.f);
            mask_out[pt] = m ? 1.0f : 0.0f;
        }
    }

    const float2* __restrict__ tbl = (const float2*)table;

    #pragma unroll
    for (int l = 0; l < NLV; ++l) {
        float f0 = 0.f, f1 = 0.f;
        if (active) {
            const float resf = (float)(BASE_RES << l);
            const float posx = xnx * resf;
            const float posy = xny * resf;
            const float posz = xnz * resf;
            const float flx = floorf(posx);
            const float fly = floorf(posy);
            const float flz = floorf(posz);
            const float fx = posx - flx;
            const float fy = posy - fly;
            const float fz = posz - flz;

            const uint32_t ux = (uint32_t)(int32_t)flx;
            const uint32_t uy = (uint32_t)(int32_t)fly;
            const uint32_t uz = (uint32_t)(int32_t)flz;

            // per-axis hash contributions (h = x*1 ^ y*P1 ^ z*P2, uint32 wrap)
            const uint32_t hx0 = ux;
            const uint32_t hx1 = ux + 1u;
            const uint32_t hy0 = uy * 2654435761u;
            const uint32_t hy1 = (uy + 1u) * 2654435761u;
            const uint32_t hz0 = uz * 805459861u;
            const uint32_t hz1 = (uz + 1u) * 805459861u;

            const uint32_t i000 = (hx0 ^ hy0 ^ hz0) & TMASK;
            const uint32_t i001 = (hx0 ^ hy0 ^ hz1) & TMASK;
            const uint32_t i010 = (hx0 ^ hy1 ^ hz0) & TMASK;
            const uint32_t i011 = (hx0 ^ hy1 ^ hz1) & TMASK;
            const uint32_t i100 = (hx1 ^ hy0 ^ hz0) & TMASK;
            const uint32_t i101 = (hx1 ^ hy0 ^ hz1) & TMASK;
            const uint32_t i110 = (hx1 ^ hy1 ^ hz0) & TMASK;
            const uint32_t i111 = (hx1 ^ hy1 ^ hz1) & TMASK;

            // issue all 8 gathers before consuming (MLP = 8)
            const float2 c000 = __ldg(tbl + i000);
            const float2 c001 = __ldg(tbl + i001);
            const float2 c010 = __ldg(tbl + i010);
            const float2 c011 = __ldg(tbl + i011);
            const float2 c100 = __ldg(tbl + i100);
            const float2 c101 = __ldg(tbl + i101);
            const float2 c110 = __ldg(tbl + i110);
            const float2 c111 = __ldg(tbl + i111);

            const float wx1 = fx, wx0 = 1.f - fx;
            const float wy1 = fy, wy0 = 1.f - fy;
            const float wz1 = fz, wz0 = 1.f - fz;

            float w;
            w = wx0 * wy0 * wz0; f0 += w * c000.x; f1 += w * c000.y;
            w = wx0 * wy0 * wz1; f0 += w * c001.x; f1 += w * c001.y;
            w = wx0 * wy1 * wz0; f0 += w * c010.x; f1 += w * c010.y;
            w = wx0 * wy1 * wz1; f0 += w * c011.x; f1 += w * c011.y;
            w = wx1 * wy0 * wz0; f0 += w * c100.x; f1 += w * c100.y;
            w = wx1 * wy0 * wz1; f0 += w * c101.x; f1 += w * c101.y;
            w = wx1 * wy1 * wz0; f0 += w * c110.x; f1 += w * c110.y;
            w = wx1 * wy1 * wz1; f0 += w * c111.x; f1 += w * c111.y;
        }
        s[tid * PAD + 2 * l + 0] = f0;
        s[tid * PAD + 2 * l + 1] = f1;
        tbl += TSIZE;
    }

    __syncthreads();

    // coalesced [N,32] output: block writes BLK*32 contiguous floats as float4s
    float4* __restrict__ out4 = (float4*)out;
    const long base4 = (long)blockIdx.x * (BLK * 8);
    #pragma unroll
    for (int i = tid; i < BLK * 8; i += BLK) {
        const int p = i >> 3;          // point within block
        const int c = i & 7;           // float4 chunk within row
        const long gp = (long)blockIdx.x * BLK + p;
        if (gp < n)
            out4[base4 + i] = *(const float4*)&s[p * PAD + c * 4];
    }
}

extern "C" void kernel_launch(void* const* d_in, const int* in_sizes, int n_in,
                              void* d_out, int out_size)
{
    const float* x     = (const float*)d_in[0];   // [N,3]
    const float* bb    = (const float*)d_in[1];   // [6]
    const float* table = (const float*)d_in[2];   // [16, 2^19, 2]

    const int n = in_sizes[0] / 3;
    float* out = (float*)d_out;

    // output layout: enc [N,32] float32, then mask [N] (0/1 float), per tuple order
    const int write_mask = (out_size >= n * 33) ? 1 : 0;
    float* mask_out = out + (size_t)n * 32;

    const int grid = (n + BLK - 1) / BLK;
    hash_enc_kernel<<<grid, BLK>>>(x, bb, table, out, mask_out, n, write_mask);
}

// round 2
// speedup vs baseline: 2.5446x; 2.5446x over previous
#include <cuda_runtime.h>
#include <stdint.h>

#define NLV 16
#define LOG2T 19
#define TSIZE (1u << LOG2T)
#define TMASK (TSIZE - 1u)
#define BASE_RES 16
#define BLK 256            // 16 points x 16 levels per block
#define PTS_PER_BLK (BLK / NLV)

__global__ __launch_bounds__(BLK) void hash_enc_lvlpar_kernel(
    const float* __restrict__ x,
    const float* __restrict__ bb,
    const float* __restrict__ table,
    float* __restrict__ out,
    float* __restrict__ mask_out,
    int n)
{
    const int tid = threadIdx.x;
    const int l = tid & (NLV - 1);          // level
    const int pl = tid >> 4;                // local point index (0..15)
    const long pt = (long)blockIdx.x * PTS_PER_BLK + pl;
    if (pt >= n) return;

    // normalize point (broadcast loads; bb is tiny, x rows shared by 16 lanes)
    const float bx0 = __ldg(bb + 0), by0 = __ldg(bb + 1), bz0 = __ldg(bb + 2);
    const float bx1 = __ldg(bb + 3), by1 = __ldg(bb + 4), bz1 = __ldg(bb + 5);
    const float px = __ldg(x + pt * 3 + 0);
    const float py = __ldg(x + pt * 3 + 1);
    const float pz = __ldg(x + pt * 3 + 2);
    const float xnx = (px - bx0) / (bx1 - bx0);
    const float xny = (py - by0) / (by1 - by0);
    const float xnz = (pz - bz0) / (bz1 - bz0);

    if (l == 0) {
        const bool m = (xnx > 0.f) & (xnx < 1.f) &
                       (xny > 0.f) & (xny < 1.f) &
                       (xnz > 0.f) & (xnz < 1.f);
        mask_out[pt] = m ? 1.0f : 0.0f;
    }

    // this level's resolution: floor(16 * 2^l) == 16 << l (exact in fp32 for l<=15)
    const float resf = (float)(BASE_RES << l);
    const float posx = xnx * resf;
    const float posy = xny * resf;
    const float posz = xnz * resf;
    const float flx = floorf(posx);
    const float fly = floorf(posy);
    const float flz = floorf(posz);
    const float fx = posx - flx;
    const float fy = posy - fly;
    const float fz = posz - flz;

    const uint32_t ux = (uint32_t)(int32_t)flx;
    const uint32_t uy = (uint32_t)(int32_t)fly;
    const uint32_t uz = (uint32_t)(int32_t)flz;

    // per-axis hash contributions: h = x*1 ^ y*P1 ^ z*P2 (uint32 wrap)
    const uint32_t hx0 = ux;
    const uint32_t hx1 = ux + 1u;
    const uint32_t hy0 = uy * 2654435761u;
    const uint32_t hy1 = (uy + 1u) * 2654435761u;
    const uint32_t hz0 = uz * 805459861u;
    const uint32_t hz1 = (uz + 1u) * 805459861u;

    const float2* __restrict__ tbl = (const float2*)table + (size_t)l * TSIZE;

    const uint32_t i000 = (hx0 ^ hy0 ^ hz0) & TMASK;
    const uint32_t i001 = (hx0 ^ hy0 ^ hz1) & TMASK;
    const uint32_t i010 = (hx0 ^ hy1 ^ hz0) & TMASK;
    const uint32_t i011 = (hx0 ^ hy1 ^ hz1) & TMASK;
    const uint32_t i100 = (hx1 ^ hy0 ^ hz0) & TMASK;
    const uint32_t i101 = (hx1 ^ hy0 ^ hz1) & TMASK;
    const uint32_t i110 = (hx1 ^ hy1 ^ hz0) & TMASK;
    const uint32_t i111 = (hx1 ^ hy1 ^ hz1) & TMASK;

    // 8 independent gathers, all in flight at once
    const float2 c000 = __ldg(tbl + i000);
    const float2 c001 = __ldg(tbl + i001);
    const float2 c010 = __ldg(tbl + i010);
    const float2 c011 = __ldg(tbl + i011);
    const float2 c100 = __ldg(tbl + i100);
    const float2 c101 = __ldg(tbl + i101);
    const float2 c110 = __ldg(tbl + i110);
    const float2 c111 = __ldg(tbl + i111);

    const float wx1 = fx, wx0 = 1.f - fx;
    const float wy1 = fy, wy0 = 1.f - fy;
    const float wz1 = fz, wz0 = 1.f - fz;

    float f0 = 0.f, f1 = 0.f, w;
    w = wx0 * wy0 * wz0; f0 += w * c000.x; f1 += w * c000.y;
    w = wx0 * wy0 * wz1; f0 += w * c001.x; f1 += w * c001.y;
    w = wx0 * wy1 * wz0; f0 += w * c010.x; f1 += w * c010.y;
    w = wx0 * wy1 * wz1; f0 += w * c011.x; f1 += w * c011.y;
    w = wx1 * wy0 * wz0; f0 += w * c100.x; f1 += w * c100.y;
    w = wx1 * wy0 * wz1; f0 += w * c101.x; f1 += w * c101.y;
    w = wx1 * wy1 * wz0; f0 += w * c110.x; f1 += w * c110.y;
    w = wx1 * wy1 * wz1; f0 += w * c111.x; f1 += w * c111.y;

    // enc[pt][2*l .. 2*l+1] — consecutive lanes write consecutive float2s (coalesced)
    float2* __restrict__ out2 = (float2*)out;
    out2[pt * NLV + l] = make_float2(f0, f1);
}

extern "C" void kernel_launch(void* const* d_in, const int* in_sizes, int n_in,
                              void* d_out, int out_size)
{
    const float* x     = (const float*)d_in[0];   // [N,3]
    const float* bb    = (const float*)d_in[1];   // [6]
    const float* table = (const float*)d_in[2];   // [16, 2^19, 2]

    const int n = in_sizes[0] / 3;
    float* out = (float*)d_out;
    float* mask_out = out + (size_t)n * 32;       // enc [N,32] then mask [N]

    const int grid = (n + PTS_PER_BLK - 1) / PTS_PER_BLK;
    hash_enc_lvlpar_kernel<<<grid, BLK>>>(x, bb, table, out, mask_out, n);
}

// round 4
// speedup vs baseline: 2.5832x; 1.0152x over previous
#include <cuda_runtime.h>
#include <stdint.h>

#define NLV 16
#define LOG2T 19
#define TSIZE (1u << LOG2T)
#define TMASK (TSIZE - 1u)
#define BASE_RES 16
#define BLK 256            // 16 points x 16 levels per block
#define PTS_PER_BLK (BLK / NLV)

// precomputed normalization: [0..2]=bb_min, [3..5]=1/(bb_max-bb_min)
__device__ float g_norm[6];

__global__ void prep_kernel(const float* __restrict__ bb)
{
    if (threadIdx.x == 0) {
        #pragma unroll
        for (int i = 0; i < 3; ++i) {
            g_norm[i]     = bb[i];
            g_norm[3 + i] = 1.0f / (bb[3 + i] - bb[i]);
        }
    }
}

__global__ __launch_bounds__(BLK) void hash_enc_lvlpar_kernel(
    const float* __restrict__ x,
    const float* __restrict__ table,
    float* __restrict__ out,
    float* __restrict__ mask_out,
    int n)
{
    const int tid = threadIdx.x;
    const int l = tid & (NLV - 1);          // level
    const int pl = tid >> 4;                // local point index (0..15)
    const long pt = (long)blockIdx.x * PTS_PER_BLK + pl;
    if (pt >= n) return;

    // normalization constants (broadcast loads, L2/L1 resident)
    const float bx0 = g_norm[0], by0 = g_norm[1], bz0 = g_norm[2];
    const float ix  = g_norm[3], iy  = g_norm[4], iz  = g_norm[5];

    const float px = __ldg(x + pt * 3 + 0);
    const float py = __ldg(x + pt * 3 + 1);
    const float pz = __ldg(x + pt * 3 + 2);
    const float xnx = (px - bx0) * ix;
    const float xny = (py - by0) * iy;
    const float xnz = (pz - bz0) * iz;

    if (l == 0) {
        const bool m = (xnx > 0.f) & (xnx < 1.f) &
                       (xny > 0.f) & (xny < 1.f) &
                       (xnz > 0.f) & (xnz < 1.f);
        mask_out[pt] = m ? 1.0f : 0.0f;
    }

    // this level's resolution: floor(16 * 2^l) == 16 << l (exact in fp32)
    const float resf = (float)(BASE_RES << l);
    const float posx = xnx * resf;
    const float posy = xny * resf;
    const float posz = xnz * resf;
    const float flx = floorf(posx);
    const float fly = floorf(posy);
    const float flz = floorf(posz);
    const float fx = posx - flx;
    const float fy = posy - fly;
    const float fz = posz - flz;

    const uint32_t ux = (uint32_t)(int32_t)flx;
    const uint32_t uy = (uint32_t)(int32_t)fly;
    const uint32_t uz = (uint32_t)(int32_t)flz;

    // per-axis hash contributions: h = x*1 ^ y*P1 ^ z*P2 (uint32 wrap)
    const uint32_t hx0 = ux;
    const uint32_t hx1 = ux + 1u;
    const uint32_t hy0 = uy * 2654435761u;
    const uint32_t hy1 = (uy + 1u) * 2654435761u;
    const uint32_t hz0 = uz * 805459861u;
    const uint32_t hz1 = (uz + 1u) * 805459861u;

    const float2* __restrict__ tbl = (const float2*)table + (size_t)l * TSIZE;

    const uint32_t i000 = (hx0 ^ hy0 ^ hz0) & TMASK;
    const uint32_t i001 = (hx0 ^ hy0 ^ hz1) & TMASK;
    const uint32_t i010 = (hx0 ^ hy1 ^ hz0) & TMASK;
    const uint32_t i011 = (hx0 ^ hy1 ^ hz1) & TMASK;
    const uint32_t i100 = (hx1 ^ hy0 ^ hz0) & TMASK;
    const uint32_t i101 = (hx1 ^ hy0 ^ hz1) & TMASK;
    const uint32_t i110 = (hx1 ^ hy1 ^ hz0) & TMASK;
    const uint32_t i111 = (hx1 ^ hy1 ^ hz1) & TMASK;

    // 8 independent gathers, all in flight at once
    const float2 c000 = __ldg(tbl + i000);
    const float2 c001 = __ldg(tbl + i001);
    const float2 c010 = __ldg(tbl + i010);
    const float2 c011 = __ldg(tbl + i011);
    const float2 c100 = __ldg(tbl + i100);
    const float2 c101 = __ldg(tbl + i101);
    const float2 c110 = __ldg(tbl + i110);
    const float2 c111 = __ldg(tbl + i111);

    const float wx1 = fx, wx0 = 1.f - fx;
    const float wy1 = fy, wy0 = 1.f - fy;
    const float wz1 = fz, wz0 = 1.f - fz;

    float f0 = 0.f, f1 = 0.f, w;
    w = wx0 * wy0 * wz0; f0 += w * c000.x; f1 += w * c000.y;
    w = wx0 * wy0 * wz1; f0 += w * c001.x; f1 += w * c001.y;
    w = wx0 * wy1 * wz0; f0 += w * c010.x; f1 += w * c010.y;
    w = wx0 * wy1 * wz1; f0 += w * c011.x; f1 += w * c011.y;
    w = wx1 * wy0 * wz0; f0 += w * c100.x; f1 += w * c100.y;
    w = wx1 * wy0 * wz1; f0 += w * c101.x; f1 += w * c101.y;
    w = wx1 * wy1 * wz0; f0 += w * c110.x; f1 += w * c110.y;
    w = wx1 * wy1 * wz1; f0 += w * c111.x; f1 += w * c111.y;

    // enc[pt][2*l .. 2*l+1] — consecutive lanes write consecutive float2s (coalesced)
    float2* __restrict__ out2 = (float2*)out;
    out2[pt * NLV + l] = make_float2(f0, f1);
}

extern "C" void kernel_launch(void* const* d_in, const int* in_sizes, int n_in,
                              void* d_out, int out_size)
{
    const float* x     = (const float*)d_in[0];   // [N,3]
    const float* bb    = (const float*)d_in[1];   // [6]
    const float* table = (const float*)d_in[2];   // [16, 2^19, 2]

    const int n = in_sizes[0] / 3;
    float* out = (float*)d_out;
    float* mask_out = out + (size_t)n * 32;       // enc [N,32] then mask [N]

    prep_kernel<<<1, 32>>>(bb);

    const int grid = (n + PTS_PER_BLK - 1) / PTS_PER_BLK;
    hash_enc_lvlpar_kernel<<<grid, BLK>>>(x, table, out, mask_out, n);
}

// round 5
// speedup vs baseline: 3.1679x; 1.2263x over previous
#include <cuda_runtime.h>
#include <stdint.h>

#define NLV 16
#define LOG2T 19
#define TSIZE (1u << LOG2T)
#define TMASK (TSIZE - 1u)
#define BASE_RES 16
#define BLK 256            // 16 points x 16 levels per block
#define PTS_PER_BLK (BLK / NLV)

// precomputed normalization: [0..2]=bb_min, [3..5]=1/(bb_max-bb_min)
__device__ float g_norm[6];

__global__ void prep_kernel(const float* __restrict__ bb)
{
    if (threadIdx.x == 0) {
        #pragma unroll
        for (int i = 0; i < 3; ++i) {
            g_norm[i]     = bb[i];
            g_norm[3 + i] = 1.0f / (bb[3 + i] - bb[i]);
        }
    }
}

__global__ __launch_bounds__(BLK) void hash_enc_lvlpar_kernel(
    const float* __restrict__ x,
    const float* __restrict__ table,
    float* __restrict__ out,
    float* __restrict__ mask_out,
    int n)
{
    const int tid = threadIdx.x;
    const int l = tid & (NLV - 1);          // level
    const int pl = tid >> 4;                // local point index (0..15)
    const long pt = (long)blockIdx.x * PTS_PER_BLK + pl;
    if (pt >= n) return;

    const float bx0 = g_norm[0], by0 = g_norm[1], bz0 = g_norm[2];
    const float ix  = g_norm[3], iy  = g_norm[4], iz  = g_norm[5];

    const float px = __ldg(x + pt * 3 + 0);
    const float py = __ldg(x + pt * 3 + 1);
    const float pz = __ldg(x + pt * 3 + 2);
    const float xnx = (px - bx0) * ix;
    const float xny = (py - by0) * iy;
    const float xnz = (pz - bz0) * iz;

    if (l == 0) {
        const bool m = (xnx > 0.f) & (xnx < 1.f) &
                       (xny > 0.f) & (xny < 1.f) &
                       (xnz > 0.f) & (xnz < 1.f);
        mask_out[pt] = m ? 1.0f : 0.0f;
    }

    // level resolution: floor(16 * 2^l) == 16 << l (exact in fp32)
    const float resf = (float)(BASE_RES << l);
    const float posx = xnx * resf;
    const float posy = xny * resf;
    const float posz = xnz * resf;
    const float flx = floorf(posx);
    const float fly = floorf(posy);
    const float flz = floorf(posz);
    const float fx = posx - flx;
    const float fy = posy - fly;
    const float fz = posz - flz;

    const uint32_t ux = (uint32_t)(int32_t)flx;
    const uint32_t uy = (uint32_t)(int32_t)fly;
    const uint32_t uz = (uint32_t)(int32_t)flz;

    // per-axis hash contributions: h = x*1 ^ y*P1 ^ z*P2 (uint32 wrap)
    const uint32_t hy0 = uy * 2654435761u;
    const uint32_t hy1 = (uy + 1u) * 2654435761u;
    const uint32_t hz0 = uz * 805459861u;
    const uint32_t hz1 = (uz + 1u) * 805459861u;

    const float2* __restrict__ tbl2 = (const float2*)table + (size_t)l * TSIZE;
    const float4* __restrict__ tbl4 = (const float4*)tbl2;

    // x0-corner indices for the 4 (y,z) combos
    const uint32_t e00 = (ux ^ hy0 ^ hz0) & TMASK;   // (x0,y0,z0)
    const uint32_t e01 = (ux ^ hy0 ^ hz1) & TMASK;   // (x0,y0,z1)
    const uint32_t e10 = (ux ^ hy1 ^ hz0) & TMASK;   // (x0,y1,z0)
    const uint32_t e11 = (ux ^ hy1 ^ hz1) & TMASK;   // (x0,y1,z1)
    // x1-corner indices (only needed when ux is odd)
    const uint32_t ux1 = ux + 1u;
    const uint32_t f00 = (ux1 ^ hy0 ^ hz0) & TMASK;
    const uint32_t f01 = (ux1 ^ hy0 ^ hz1) & TMASK;
    const uint32_t f10 = (ux1 ^ hy1 ^ hz0) & TMASK;
    const uint32_t f11 = (ux1 ^ hy1 ^ hz1) & TMASK;

    const bool ux_odd = (ux & 1u) != 0u;

    // 4 paired gathers (each float4 covers entries {e&~1, e|1}); when ux even,
    // the pair IS {x0,x1} corners (i_x1 = i_x0 ^ 1 since PRIME_x == 1).
    const float4 q00 = __ldg(tbl4 + (e00 >> 1));
    const float4 q01 = __ldg(tbl4 + (e01 >> 1));
    const float4 q10 = __ldg(tbl4 + (e10 >> 1));
    const float4 q11 = __ldg(tbl4 + (e11 >> 1));

    // predicated extra gathers for odd ux (x1 corners not adjacent then)
    float2 d00, d01, d10, d11;
    if (ux_odd) {
        d00 = __ldg(tbl2 + f00);
        d01 = __ldg(tbl2 + f01);
        d10 = __ldg(tbl2 + f10);
        d11 = __ldg(tbl2 + f11);
    }

    const bool h00 = (e00 & 1u), h01 = (e01 & 1u), h10 = (e10 & 1u), h11 = (e11 & 1u);

    // x0 corners: select proper half of the float4
    const float2 c000 = h00 ? make_float2(q00.z, q00.w) : make_float2(q00.x, q00.y);
    const float2 c001 = h01 ? make_float2(q01.z, q01.w) : make_float2(q01.x, q01.y);
    const float2 c010 = h10 ? make_float2(q10.z, q10.w) : make_float2(q10.x, q10.y);
    const float2 c011 = h11 ? make_float2(q11.z, q11.w) : make_float2(q11.x, q11.y);

    // x1 corners: other half when even, separate load when odd
    float2 c100 = h00 ? make_float2(q00.x, q00.y) : make_float2(q00.z, q00.w);
    float2 c101 = h01 ? make_float2(q01.x, q01.y) : make_float2(q01.z, q01.w);
    float2 c110 = h10 ? make_float2(q10.x, q10.y) : make_float2(q10.z, q10.w);
    float2 c111 = h11 ? make_float2(q11.x, q11.y) : make_float2(q11.z, q11.w);
    if (ux_odd) { c100 = d00; c101 = d01; c110 = d10; c111 = d11; }

    const float wx1 = fx, wx0 = 1.f - fx;
    const float wy1 = fy, wy0 = 1.f - fy;
    const float wz1 = fz, wz0 = 1.f - fz;

    float f0 = 0.f, f1 = 0.f, w;
    w = wx0 * wy0 * wz0; f0 += w * c000.x; f1 += w * c000.y;
    w = wx0 * wy0 * wz1; f0 += w * c001.x; f1 += w * c001.y;
    w = wx0 * wy1 * wz0; f0 += w * c010.x; f1 += w * c010.y;
    w = wx0 * wy1 * wz1; f0 += w * c011.x; f1 += w * c011.y;
    w = wx1 * wy0 * wz0; f0 += w * c100.x; f1 += w * c100.y;
    w = wx1 * wy0 * wz1; f0 += w * c101.x; f1 += w * c101.y;
    w = wx1 * wy1 * wz0; f0 += w * c110.x; f1 += w * c110.y;
    w = wx1 * wy1 * wz1; f0 += w * c111.x; f1 += w * c111.y;

    float2* __restrict__ out2 = (float2*)out;
    out2[pt * NLV + l] = make_float2(f0, f1);
}

extern "C" void kernel_launch(void* const* d_in, const int* in_sizes, int n_in,
                              void* d_out, int out_size)
{
    const float* x     = (const float*)d_in[0];   // [N,3]
    const float* bb    = (const float*)d_in[1];   // [6]
    const float* table = (const float*)d_in[2];   // [16, 2^19, 2]

    const int n = in_sizes[0] / 3;
    float* out = (float*)d_out;
    float* mask_out = out + (size_t)n * 32;       // enc [N,32] then mask [N]

    prep_kernel<<<1, 32>>>(bb);

    const int grid = (n + PTS_PER_BLK - 1) / PTS_PER_BLK;
    hash_enc_lvlpar_kernel<<<grid, BLK>>>(x, table, out, mask_out, n);
}